// round 1
// baseline (speedup 1.0000x reference)
#include <cuda_runtime.h>
#include <cstdint>

// Problem constants
#define BATCH   8
#define NHID    256
#define LEN     2048
#define NHEAD   8
#define HDIM    64
#define DD      512      // NHEAD*HDIM (q/k/v channels)
#define DOUT    2048     // NHEAD*NHID (output channels)
#define MM      (BATCH*LEN)  // 16384 rows

// GEMM tiling
#define BM 128
#define BN 128
#define BK 16
#define TM 8
#define TN 8
#define NTHREADS 256

// Scratch (static device allocations — no cudaMalloc allowed)
__device__ float g_q[MM * DD];
__device__ float g_k[MM * DD];
__device__ float g_v[MM * DD];
__device__ float g_att[MM * DD];

// ---- packed f32x2 helpers (PTX-only path, doubles FFMA throughput) ----
__device__ __forceinline__ unsigned long long pk2(float lo, float hi) {
    unsigned long long r;
    asm("mov.b64 %0, {%1, %2};" : "=l"(r) : "f"(lo), "f"(hi));
    return r;
}
__device__ __forceinline__ float2 upk2(unsigned long long v) {
    float2 r;
    asm("mov.b64 {%0, %1}, %2;" : "=f"(r.x), "=f"(r.y) : "l"(v));
    return r;
}
__device__ __forceinline__ void fma2(unsigned long long& d,
                                     unsigned long long a,
                                     unsigned long long b) {
    asm("fma.rn.f32x2 %0, %1, %2, %0;" : "+l"(d) : "l"(a), "l"(b));
}

// ============================================================================
// GEMM1: q/k/v = x^T @ W + b.   x is [B, NHID, L] so A-tile loads are
// coalesced along l and land directly in K-major smem (fused transpose).
// grid = (M/BM, DD/BN, 3)   z selects (Wq,bq,g_q)/(Wk,..)/(Wv,..)
// ============================================================================
__global__ __launch_bounds__(NTHREADS)
void gemm_qkv_kernel(const float* __restrict__ x,
                     const float* __restrict__ Wq, const float* __restrict__ bq,
                     const float* __restrict__ Wk, const float* __restrict__ bk,
                     const float* __restrict__ Wv, const float* __restrict__ bv) {
    const float* W; const float* bias; float* out;
    if (blockIdx.z == 0)      { W = Wq; bias = bq; out = g_q; }
    else if (blockIdx.z == 1) { W = Wk; bias = bk; out = g_k; }
    else                      { W = Wv; bias = bv; out = g_v; }

    const int m0 = blockIdx.x * BM;
    const int n0 = blockIdx.y * BN;
    const int b  = m0 / LEN;        // BM divides LEN -> tile within one batch
    const int l0 = m0 % LEN;

    __shared__ float As[BK][BM];    // As[k][m]
    __shared__ float Bs[BK][BN];    // Bs[k][n]

    const int tid = threadIdx.x;
    const int tm  = tid / (BN / TN);   // 0..15
    const int tn  = tid % (BN / TN);   // 0..15

    unsigned long long acc2[TM][TN / 2];
    #pragma unroll
    for (int i = 0; i < TM; i++)
        #pragma unroll
        for (int j = 0; j < TN / 2; j++) acc2[i][j] = pk2(0.f, 0.f);

    const float* xb = x + (size_t)b * NHID * LEN;

    for (int k0 = 0; k0 < NHID; k0 += BK) {
        #pragma unroll
        for (int r = 0; r < 2; r++) {
            int linear = tid + r * NTHREADS;          // 0..511
            int kk = linear >> 5;                     // 0..15
            int mm = (linear & 31) << 2;              // 0,4,..,124
            float4 v4 = *reinterpret_cast<const float4*>(
                &xb[(size_t)(k0 + kk) * LEN + l0 + mm]);
            *reinterpret_cast<float4*>(&As[kk][mm]) = v4;
        }
        #pragma unroll
        for (int r = 0; r < 2; r++) {
            int linear = tid + r * NTHREADS;
            int kk = linear >> 5;
            int nn = (linear & 31) << 2;
            float4 v4 = *reinterpret_cast<const float4*>(
                &W[(size_t)(k0 + kk) * DD + n0 + nn]);
            *reinterpret_cast<float4*>(&Bs[kk][nn]) = v4;
        }
        __syncthreads();

        #pragma unroll
        for (int kk = 0; kk < BK; kk++) {
            float4 a0 = *reinterpret_cast<const float4*>(&As[kk][tm * TM]);
            float4 a1 = *reinterpret_cast<const float4*>(&As[kk][tm * TM + 4]);
            float4 b0 = *reinterpret_cast<const float4*>(&Bs[kk][tn * TN]);
            float4 b1 = *reinterpret_cast<const float4*>(&Bs[kk][tn * TN + 4]);
            unsigned long long bb[4] = { pk2(b0.x, b0.y), pk2(b0.z, b0.w),
                                         pk2(b1.x, b1.y), pk2(b1.z, b1.w) };
            float aa[8] = { a0.x, a0.y, a0.z, a0.w, a1.x, a1.y, a1.z, a1.w };
            #pragma unroll
            for (int i = 0; i < TM; i++) {
                unsigned long long ai = pk2(aa[i], aa[i]);
                #pragma unroll
                for (int j = 0; j < TN / 2; j++) fma2(acc2[i][j], ai, bb[j]);
            }
        }
        __syncthreads();
    }

    #pragma unroll
    for (int i = 0; i < TM; i++) {
        const int m = m0 + tm * TM + i;
        const int n = n0 + tn * TN;
        float2 p0 = upk2(acc2[i][0]);
        float2 p1 = upk2(acc2[i][1]);
        float2 p2 = upk2(acc2[i][2]);
        float2 p3 = upk2(acc2[i][3]);
        float4 r0 = { p0.x + bias[n + 0], p0.y + bias[n + 1],
                      p1.x + bias[n + 2], p1.y + bias[n + 3] };
        float4 r1 = { p2.x + bias[n + 4], p2.y + bias[n + 5],
                      p3.x + bias[n + 6], p3.y + bias[n + 7] };
        *reinterpret_cast<float4*>(&out[(size_t)m * DD + n])     = r0;
        *reinterpret_cast<float4*>(&out[(size_t)m * DD + n + 4]) = r1;
    }
}

// ============================================================================
// Attention: per (m, head): scores over window of 3, softmax, weighted V sum.
// Zero-padded boundaries -> OOB window positions have score exactly 0 and v=0
// (matches reference: pad-with-zero k gives dot==0, included in softmax).
// grid = M blocks, 256 threads (8 warps = 8 heads, lane handles 2 h-values).
// ============================================================================
__global__ __launch_bounds__(NTHREADS)
void attn_kernel() {
    const int m    = blockIdx.x;
    const int b    = m >> 11;         // /LEN
    const int l    = m & (LEN - 1);
    const int head = threadIdx.x >> 5;
    const int lane = threadIdx.x & 31;

    const size_t base = (size_t)m * DD + head * HDIM + lane * 2;
    const float2 q = *reinterpret_cast<const float2*>(&g_q[base]);

    float s[3];
    float2 vv[3];
    #pragma unroll
    for (int w = 0; w < 3; w++) {
        const int lw = l + w - 1;
        float2 kk = make_float2(0.f, 0.f);
        float2 v2 = make_float2(0.f, 0.f);
        if (lw >= 0 && lw < LEN) {
            const size_t off = (size_t)(b * LEN + lw) * DD + head * HDIM + lane * 2;
            kk = *reinterpret_cast<const float2*>(&g_k[off]);
            v2 = *reinterpret_cast<const float2*>(&g_v[off]);
        }
        float p = q.x * kk.x + q.y * kk.y;
        #pragma unroll
        for (int o = 16; o; o >>= 1) p += __shfl_xor_sync(0xffffffffu, p, o);
        s[w] = p * 0.125f;   // 1/sqrt(64)
        vv[w] = v2;
    }

    const float mx = fmaxf(s[0], fmaxf(s[1], s[2]));
    const float e0 = __expf(s[0] - mx);
    const float e1 = __expf(s[1] - mx);
    const float e2 = __expf(s[2] - mx);
    const float inv = 1.f / (e0 + e1 + e2);

    float2 o;
    o.x = (e0 * vv[0].x + e1 * vv[1].x + e2 * vv[2].x) * inv;
    o.y = (e0 * vv[0].y + e1 * vv[1].y + e2 * vv[2].y) * inv;
    *reinterpret_cast<float2*>(&g_att[base]) = o;
}

// ============================================================================
// GEMM2 (output-transposed): C'[n, l] = sum_k Wo[k,n] * att[m,k] + bo[n],
// written to out[b, n, l] = out[(b*DOUT + n)*L + l]. Computing the transpose
// directly keeps the 128MB store float4-coalesced.
// grid = (DOUT/BM, M/BN)
// ============================================================================
__global__ __launch_bounds__(NTHREADS)
void gemm_out_kernel(const float* __restrict__ Wo,
                     const float* __restrict__ bo,
                     float* __restrict__ out) {
    const int n0 = blockIdx.x * BM;   // rows of C' = output channel n
    const int m0 = blockIdx.y * BN;   // cols of C' = sequence position m
    const int b  = m0 / LEN;
    const int l0 = m0 % LEN;

    __shared__ float As[BK][BM];    // As[k][n] = Wo[k, n]  (direct coalesced)
    __shared__ float Bs[BK][BN];    // Bs[k][m] = att[m, k] (transpose on load)

    const int tid = threadIdx.x;
    const int tm  = tid / (BN / TN);
    const int tn  = tid % (BN / TN);

    unsigned long long acc2[TM][TN / 2];
    #pragma unroll
    for (int i = 0; i < TM; i++)
        #pragma unroll
        for (int j = 0; j < TN / 2; j++) acc2[i][j] = pk2(0.f, 0.f);

    for (int k0 = 0; k0 < DD; k0 += BK) {
        // A: Wo[(k0+kk)*DOUT + n0+nn] — contiguous along n
        #pragma unroll
        for (int r = 0; r < 2; r++) {
            int linear = tid + r * NTHREADS;
            int kk = linear >> 5;
            int nn = (linear & 31) << 2;
            float4 v4 = *reinterpret_cast<const float4*>(
                &Wo[(size_t)(k0 + kk) * DOUT + n0 + nn]);
            *reinterpret_cast<float4*>(&As[kk][nn]) = v4;
        }
        // B: att[(m0+mm)*DD + k0+kq..] — float4 along k, scattered into smem
        #pragma unroll
        for (int r = 0; r < 2; r++) {
            int linear = tid + r * NTHREADS;          // 0..511
            int mm = linear >> 2;                     // 0..127
            int kq = (linear & 3) << 2;               // 0,4,8,12
            float4 t = *reinterpret_cast<const float4*>(
                &g_att[(size_t)(m0 + mm) * DD + k0 + kq]);
            Bs[kq + 0][mm] = t.x;
            Bs[kq + 1][mm] = t.y;
            Bs[kq + 2][mm] = t.z;
            Bs[kq + 3][mm] = t.w;
        }
        __syncthreads();

        #pragma unroll
        for (int kk = 0; kk < BK; kk++) {
            float4 a0 = *reinterpret_cast<const float4*>(&As[kk][tm * TM]);
            float4 a1 = *reinterpret_cast<const float4*>(&As[kk][tm * TM + 4]);
            float4 b0 = *reinterpret_cast<const float4*>(&Bs[kk][tn * TN]);
            float4 b1 = *reinterpret_cast<const float4*>(&Bs[kk][tn * TN + 4]);
            unsigned long long bb[4] = { pk2(b0.x, b0.y), pk2(b0.z, b0.w),
                                         pk2(b1.x, b1.y), pk2(b1.z, b1.w) };
            float aa[8] = { a0.x, a0.y, a0.z, a0.w, a1.x, a1.y, a1.z, a1.w };
            #pragma unroll
            for (int i = 0; i < TM; i++) {
                unsigned long long ai = pk2(aa[i], aa[i]);
                #pragma unroll
                for (int j = 0; j < TN / 2; j++) fma2(acc2[i][j], ai, bb[j]);
            }
        }
        __syncthreads();
    }

    #pragma unroll
    for (int i = 0; i < TM; i++) {
        const int nrow = n0 + tm * TM + i;
        const float bias = bo[nrow];
        float* op = out + ((size_t)(b * DOUT + nrow)) * LEN + l0 + tn * TN;
        float2 p0 = upk2(acc2[i][0]);
        float2 p1 = upk2(acc2[i][1]);
        float2 p2 = upk2(acc2[i][2]);
        float2 p3 = upk2(acc2[i][3]);
        float4 r0 = { p0.x + bias, p0.y + bias, p1.x + bias, p1.y + bias };
        float4 r1 = { p2.x + bias, p2.y + bias, p3.x + bias, p3.y + bias };
        *reinterpret_cast<float4*>(&op[0]) = r0;
        *reinterpret_cast<float4*>(&op[4]) = r1;
    }
}

// ============================================================================
extern "C" void kernel_launch(void* const* d_in, const int* in_sizes, int n_in,
                              void* d_out, int out_size) {
    const float* x  = (const float*)d_in[0];
    const float* Wq = (const float*)d_in[1];
    const float* bq = (const float*)d_in[2];
    const float* Wk = (const float*)d_in[3];
    const float* bk = (const float*)d_in[4];
    const float* Wv = (const float*)d_in[5];
    const float* bv = (const float*)d_in[6];
    const float* Wo = (const float*)d_in[7];
    const float* bo = (const float*)d_in[8];
    float* out = (float*)d_out;

    gemm_qkv_kernel<<<dim3(MM / BM, DD / BN, 3), NTHREADS>>>(x, Wq, bq, Wk, bk, Wv, bv);
    attn_kernel<<<MM, NTHREADS>>>();
    gemm_out_kernel<<<dim3(DOUT / BM, MM / BN), NTHREADS>>>(Wo, bo, out);
}

// round 2
// speedup vs baseline: 1.0565x; 1.0565x over previous
#include <cuda_runtime.h>
#include <cstdint>

// Problem constants
#define BATCH   8
#define NHID    256
#define LEN     2048
#define NHEAD   8
#define HDIM    64
#define DD      512      // NHEAD*HDIM (q/k/v channels)
#define DOUT    2048     // NHEAD*NHID (output channels)
#define MM      (BATCH*LEN)  // 16384 rows

// GEMM tiling
#define BM 128
#define BN 128
#define BK 16
#define TM 8
#define TN 8
#define NTHREADS 256

// Scratch (static device allocations — no cudaMalloc allowed)
__device__ float g_q[MM * DD];
__device__ float g_k[MM * DD];
__device__ float g_v[MM * DD];
__device__ float g_att[MM * DD];

// ---- packed f32x2 helpers (PTX-only path, doubles FFMA throughput) ----
__device__ __forceinline__ unsigned long long pk2(float lo, float hi) {
    unsigned long long r;
    asm("mov.b64 %0, {%1, %2};" : "=l"(r) : "f"(lo), "f"(hi));
    return r;
}
__device__ __forceinline__ float2 upk2(unsigned long long v) {
    float2 r;
    asm("mov.b64 {%0, %1}, %2;" : "=f"(r.x), "=f"(r.y) : "l"(v));
    return r;
}
__device__ __forceinline__ void fma2(unsigned long long& d,
                                     unsigned long long a,
                                     unsigned long long b) {
    asm("fma.rn.f32x2 %0, %1, %2, %0;" : "+l"(d) : "l"(a), "l"(b));
}

// ============================================================================
// GEMM1: q/k/v = x^T @ W + b.   x is [B, NHID, L] so A-tile loads are
// coalesced along l and land directly in K-major smem (fused transpose).
// grid = (M/BM, DD/BN, 3)   z selects (Wq,bq,g_q)/(Wk,..)/(Wv,..)
// ============================================================================
__global__ __launch_bounds__(NTHREADS)
void gemm_qkv_kernel(const float* __restrict__ x,
                     const float* __restrict__ Wq, const float* __restrict__ bq,
                     const float* __restrict__ Wk, const float* __restrict__ bk,
                     const float* __restrict__ Wv, const float* __restrict__ bv) {
    const float* W; const float* bias; float* out;
    if (blockIdx.z == 0)      { W = Wq; bias = bq; out = g_q; }
    else if (blockIdx.z == 1) { W = Wk; bias = bk; out = g_k; }
    else                      { W = Wv; bias = bv; out = g_v; }

    const int m0 = blockIdx.x * BM;
    const int n0 = blockIdx.y * BN;
    const int b  = m0 / LEN;        // BM divides LEN -> tile within one batch
    const int l0 = m0 % LEN;

    __shared__ float As[BK][BM];    // As[k][m]
    __shared__ float Bs[BK][BN];    // Bs[k][n]

    const int tid = threadIdx.x;
    const int tm  = tid / (BN / TN);   // 0..15
    const int tn  = tid % (BN / TN);   // 0..15

    unsigned long long acc2[TM][TN / 2];
    #pragma unroll
    for (int i = 0; i < TM; i++)
        #pragma unroll
        for (int j = 0; j < TN / 2; j++) acc2[i][j] = pk2(0.f, 0.f);

    const float* xb = x + (size_t)b * NHID * LEN;

    for (int k0 = 0; k0 < NHID; k0 += BK) {
        #pragma unroll
        for (int r = 0; r < 2; r++) {
            int linear = tid + r * NTHREADS;          // 0..511
            int kk = linear >> 5;                     // 0..15
            int mm = (linear & 31) << 2;              // 0,4,..,124
            float4 v4 = *reinterpret_cast<const float4*>(
                &xb[(size_t)(k0 + kk) * LEN + l0 + mm]);
            *reinterpret_cast<float4*>(&As[kk][mm]) = v4;
        }
        #pragma unroll
        for (int r = 0; r < 2; r++) {
            int linear = tid + r * NTHREADS;
            int kk = linear >> 5;
            int nn = (linear & 31) << 2;
            float4 v4 = *reinterpret_cast<const float4*>(
                &W[(size_t)(k0 + kk) * DD + n0 + nn]);
            *reinterpret_cast<float4*>(&Bs[kk][nn]) = v4;
        }
        __syncthreads();

        #pragma unroll
        for (int kk = 0; kk < BK; kk++) {
            float4 a0 = *reinterpret_cast<const float4*>(&As[kk][tm * TM]);
            float4 a1 = *reinterpret_cast<const float4*>(&As[kk][tm * TM + 4]);
            float4 b0 = *reinterpret_cast<const float4*>(&Bs[kk][tn * TN]);
            float4 b1 = *reinterpret_cast<const float4*>(&Bs[kk][tn * TN + 4]);
            unsigned long long bb[4] = { pk2(b0.x, b0.y), pk2(b0.z, b0.w),
                                         pk2(b1.x, b1.y), pk2(b1.z, b1.w) };
            float aa[8] = { a0.x, a0.y, a0.z, a0.w, a1.x, a1.y, a1.z, a1.w };
            #pragma unroll
            for (int i = 0; i < TM; i++) {
                unsigned long long ai = pk2(aa[i], aa[i]);
                #pragma unroll
                for (int j = 0; j < TN / 2; j++) fma2(acc2[i][j], ai, bb[j]);
            }
        }
        __syncthreads();
    }

    #pragma unroll
    for (int i = 0; i < TM; i++) {
        const int m = m0 + tm * TM + i;
        const int n = n0 + tn * TN;
        float2 p0 = upk2(acc2[i][0]);
        float2 p1 = upk2(acc2[i][1]);
        float2 p2 = upk2(acc2[i][2]);
        float2 p3 = upk2(acc2[i][3]);
        float4 r0 = { p0.x + bias[n + 0], p0.y + bias[n + 1],
                      p1.x + bias[n + 2], p1.y + bias[n + 3] };
        float4 r1 = { p2.x + bias[n + 4], p2.y + bias[n + 5],
                      p3.x + bias[n + 6], p3.y + bias[n + 7] };
        *reinterpret_cast<float4*>(&out[(size_t)m * DD + n])     = r0;
        *reinterpret_cast<float4*>(&out[(size_t)m * DD + n + 4]) = r1;
    }
}

// ============================================================================
// Attention: per (m, head): scores over window of 3, softmax, weighted V sum.
// Zero-padded boundaries -> OOB window positions have score exactly 0 and v=0
// (matches reference: pad-with-zero k gives dot==0, included in softmax).
// grid = M blocks, 256 threads (8 warps = 8 heads, lane handles 2 h-values).
// ============================================================================
__global__ __launch_bounds__(NTHREADS)
void attn_kernel() {
    const int m    = blockIdx.x;
    const int b    = m >> 11;         // /LEN
    const int l    = m & (LEN - 1);
    const int head = threadIdx.x >> 5;
    const int lane = threadIdx.x & 31;

    const size_t base = (size_t)m * DD + head * HDIM + lane * 2;
    const float2 q = *reinterpret_cast<const float2*>(&g_q[base]);

    float s[3];
    float2 vv[3];
    #pragma unroll
    for (int w = 0; w < 3; w++) {
        const int lw = l + w - 1;
        float2 kk = make_float2(0.f, 0.f);
        float2 v2 = make_float2(0.f, 0.f);
        if (lw >= 0 && lw < LEN) {
            const size_t off = (size_t)(b * LEN + lw) * DD + head * HDIM + lane * 2;
            kk = *reinterpret_cast<const float2*>(&g_k[off]);
            v2 = *reinterpret_cast<const float2*>(&g_v[off]);
        }
        float p = q.x * kk.x + q.y * kk.y;
        #pragma unroll
        for (int o = 16; o; o >>= 1) p += __shfl_xor_sync(0xffffffffu, p, o);
        s[w] = p * 0.125f;   // 1/sqrt(64)
        vv[w] = v2;
    }

    const float mx = fmaxf(s[0], fmaxf(s[1], s[2]));
    const float e0 = __expf(s[0] - mx);
    const float e1 = __expf(s[1] - mx);
    const float e2 = __expf(s[2] - mx);
    const float inv = 1.f / (e0 + e1 + e2);

    float2 o;
    o.x = (e0 * vv[0].x + e1 * vv[1].x + e2 * vv[2].x) * inv;
    o.y = (e0 * vv[0].y + e1 * vv[1].y + e2 * vv[2].y) * inv;
    *reinterpret_cast<float2*>(&g_att[base]) = o;
}

// ============================================================================
// GEMM2 (output-transposed): C'[n, l] = sum_k Wo[k,n] * att[m,k] + bo[n],
// written to out[b, n, l] = out[(b*DOUT + n)*L + l]. Computing the transpose
// directly keeps the 128MB store float4-coalesced.
// grid = (DOUT/BM, M/BN)
// ============================================================================
__global__ __launch_bounds__(NTHREADS)
void gemm_out_kernel(const float* __restrict__ Wo,
                     const float* __restrict__ bo,
                     float* __restrict__ out) {
    const int n0 = blockIdx.x * BM;   // rows of C' = output channel n
    const int m0 = blockIdx.y * BN;   // cols of C' = sequence position m
    const int b  = m0 / LEN;
    const int l0 = m0 % LEN;

    __shared__ float As[BK][BM];    // As[k][n] = Wo[k, n]  (direct coalesced)
    __shared__ float Bs[BK][BN];    // Bs[k][m] = att[m, k] (transpose on load)

    const int tid = threadIdx.x;
    const int tm  = tid / (BN / TN);
    const int tn  = tid % (BN / TN);

    unsigned long long acc2[TM][TN / 2];
    #pragma unroll
    for (int i = 0; i < TM; i++)
        #pragma unroll
        for (int j = 0; j < TN / 2; j++) acc2[i][j] = pk2(0.f, 0.f);

    for (int k0 = 0; k0 < DD; k0 += BK) {
        // A: Wo[(k0+kk)*DOUT + n0+nn] — contiguous along n
        #pragma unroll
        for (int r = 0; r < 2; r++) {
            int linear = tid + r * NTHREADS;
            int kk = linear >> 5;
            int nn = (linear & 31) << 2;
            float4 v4 = *reinterpret_cast<const float4*>(
                &Wo[(size_t)(k0 + kk) * DOUT + n0 + nn]);
            *reinterpret_cast<float4*>(&As[kk][nn]) = v4;
        }
        // B: att[(m0+mm)*DD + k0+kq..] — float4 along k, scattered into smem
        #pragma unroll
        for (int r = 0; r < 2; r++) {
            int linear = tid + r * NTHREADS;          // 0..511
            int mm = linear >> 2;                     // 0..127
            int kq = (linear & 3) << 2;               // 0,4,8,12
            float4 t = *reinterpret_cast<const float4*>(
                &g_att[(size_t)(m0 + mm) * DD + k0 + kq]);
            Bs[kq + 0][mm] = t.x;
            Bs[kq + 1][mm] = t.y;
            Bs[kq + 2][mm] = t.z;
            Bs[kq + 3][mm] = t.w;
        }
        __syncthreads();

        #pragma unroll
        for (int kk = 0; kk < BK; kk++) {
            float4 a0 = *reinterpret_cast<const float4*>(&As[kk][tm * TM]);
            float4 a1 = *reinterpret_cast<const float4*>(&As[kk][tm * TM + 4]);
            float4 b0 = *reinterpret_cast<const float4*>(&Bs[kk][tn * TN]);
            float4 b1 = *reinterpret_cast<const float4*>(&Bs[kk][tn * TN + 4]);
            unsigned long long bb[4] = { pk2(b0.x, b0.y), pk2(b0.z, b0.w),
                                         pk2(b1.x, b1.y), pk2(b1.z, b1.w) };
            float aa[8] = { a0.x, a0.y, a0.z, a0.w, a1.x, a1.y, a1.z, a1.w };
            #pragma unroll
            for (int i = 0; i < TM; i++) {
                unsigned long long ai = pk2(aa[i], aa[i]);
                #pragma unroll
                for (int j = 0; j < TN / 2; j++) fma2(acc2[i][j], ai, bb[j]);
            }
        }
        __syncthreads();
    }

    #pragma unroll
    for (int i = 0; i < TM; i++) {
        const int nrow = n0 + tm * TM + i;
        const float bias = bo[nrow];
        float* op = out + ((size_t)(b * DOUT + nrow)) * LEN + l0 + tn * TN;
        float2 p0 = upk2(acc2[i][0]);
        float2 p1 = upk2(acc2[i][1]);
        float2 p2 = upk2(acc2[i][2]);
        float2 p3 = upk2(acc2[i][3]);
        float4 r0 = { p0.x + bias, p0.y + bias, p1.x + bias, p1.y + bias };
        float4 r1 = { p2.x + bias, p2.y + bias, p3.x + bias, p3.y + bias };
        *reinterpret_cast<float4*>(&op[0]) = r0;
        *reinterpret_cast<float4*>(&op[4]) = r1;
    }
}

// ============================================================================
extern "C" void kernel_launch(void* const* d_in, const int* in_sizes, int n_in,
                              void* d_out, int out_size) {
    const float* x  = (const float*)d_in[0];
    const float* Wq = (const float*)d_in[1];
    const float* bq = (const float*)d_in[2];
    const float* Wk = (const float*)d_in[3];
    const float* bk = (const float*)d_in[4];
    const float* Wv = (const float*)d_in[5];
    const float* bv = (const float*)d_in[6];
    const float* Wo = (const float*)d_in[7];
    const float* bo = (const float*)d_in[8];
    float* out = (float*)d_out;

    gemm_qkv_kernel<<<dim3(MM / BM, DD / BN, 3), NTHREADS>>>(x, Wq, bq, Wk, bk, Wv, bv);
    attn_kernel<<<MM, NTHREADS>>>();
    gemm_out_kernel<<<dim3(DOUT / BM, MM / BN), NTHREADS>>>(Wo, bo, out);
}

// round 5
// speedup vs baseline: 1.5074x; 1.4269x over previous
#include <cuda_runtime.h>
#include <cuda_bf16.h>
#include <cstdint>

#define BATCH 8
#define NHID 256
#define LEN 2048
#define DD 512
#define DOUT 2048
#define MM (BATCH*LEN)

#define BM 128
#define BN 128
#define BK 32
#define NTHREADS 256
#define STAGES 4
// stage: A_hi(8K) A_lo(8K) B_hi(8K) B_lo(8K) = 32KB
#define MAT_BYTES 8192
#define STAGE_BYTES (4*MAT_BYTES)
#define SMEM_BYTES (STAGES*STAGE_BYTES)

// fp32 scratch
__device__ __align__(128) float g_q[MM*DD];
__device__ __align__(128) float g_k[MM*DD];
__device__ __align__(128) float g_v[MM*DD];
// bf16 split operands
__device__ __align__(128) __nv_bfloat16 g_xt_hi[MM*NHID];
__device__ __align__(128) __nv_bfloat16 g_xt_lo[MM*NHID];
__device__ __align__(128) __nv_bfloat16 g_wq_hi[DD*NHID];
__device__ __align__(128) __nv_bfloat16 g_wq_lo[DD*NHID];
__device__ __align__(128) __nv_bfloat16 g_wk_hi[DD*NHID];
__device__ __align__(128) __nv_bfloat16 g_wk_lo[DD*NHID];
__device__ __align__(128) __nv_bfloat16 g_wv_hi[DD*NHID];
__device__ __align__(128) __nv_bfloat16 g_wv_lo[DD*NHID];
__device__ __align__(128) __nv_bfloat16 g_wo_hi[DOUT*DD];
__device__ __align__(128) __nv_bfloat16 g_wo_lo[DOUT*DD];
__device__ __align__(128) __nv_bfloat16 g_att_hi[MM*DD];
__device__ __align__(128) __nv_bfloat16 g_att_lo[MM*DD];

__device__ __forceinline__ uint32_t s2u(const void* p){
    uint32_t a; asm("{ .reg .u64 t; cvta.to.shared.u64 t, %1; cvt.u32.u64 %0, t; }":"=r"(a):"l"(p)); return a; }
__device__ __forceinline__ void cpa16(uint32_t s, const void* g){
    asm volatile("cp.async.cg.shared.global [%0], [%1], 16;"::"r"(s),"l"(g):"memory"); }
#define CPA_COMMIT() asm volatile("cp.async.commit_group;":::"memory")
#define CPA_WAIT(n)  asm volatile("cp.async.wait_group %0;"::"n"(n):"memory")

__device__ __forceinline__ void ldm4(uint32_t a, uint32_t* r){
    asm volatile("ldmatrix.sync.aligned.m8n8.x4.shared.b16 {%0,%1,%2,%3}, [%4];"
        :"=r"(r[0]),"=r"(r[1]),"=r"(r[2]),"=r"(r[3]):"r"(a)); }
__device__ __forceinline__ void ldm2(uint32_t a, uint32_t* r){
    asm volatile("ldmatrix.sync.aligned.m8n8.x2.shared.b16 {%0,%1}, [%2];"
        :"=r"(r[0]),"=r"(r[1]):"r"(a)); }
__device__ __forceinline__ void mma16816(float* d, const uint32_t* a, const uint32_t* b){
    asm volatile("mma.sync.aligned.m16n8k16.row.col.f32.bf16.bf16.f32 "
        "{%0,%1,%2,%3}, {%4,%5,%6,%7}, {%8,%9}, {%0,%1,%2,%3};"
        :"+f"(d[0]),"+f"(d[1]),"+f"(d[2]),"+f"(d[3])
        :"r"(a[0]),"r"(a[1]),"r"(a[2]),"r"(a[3]),"r"(b[0]),"r"(b[1])); }

// 16B-unit XOR swizzle: rows of 32 bf16 = 4 units; phys = r*4 + (u ^ ((r>>1)&3))
__device__ __forceinline__ uint32_t swz(int r, int u){
    return (uint32_t)((r*4 + (u ^ ((r>>1)&3))) * 16);
}

// fill one stage (no commit): A rows m0..m0+127, B rows n0..n0+127, k0..k0+31
__device__ __forceinline__ void fill_stage(uint32_t sbase,
        const __nv_bfloat16* __restrict__ Ah, const __nv_bfloat16* __restrict__ Al,
        const __nv_bfloat16* __restrict__ Bh, const __nv_bfloat16* __restrict__ Bl,
        int K, int m0, int n0, int k0, int tid){
    #pragma unroll
    for (int j = 0; j < 2; j++){
        int i = tid + j*NTHREADS;          // 0..511
        int r = i >> 2, u = i & 3;
        uint32_t sw = swz(r, u);
        size_t gA = (size_t)(m0 + r)*K + k0 + u*8;
        size_t gB = (size_t)(n0 + r)*K + k0 + u*8;
        cpa16(sbase + 0*MAT_BYTES + sw, Ah + gA);
        cpa16(sbase + 1*MAT_BYTES + sw, Al + gA);
        cpa16(sbase + 2*MAT_BYTES + sw, Bh + gB);
        cpa16(sbase + 3*MAT_BYTES + sw, Bl + gB);
    }
}

// mode 0: out[(m0+r)*DD + (n0+col)] + bias[col]        (GEMM1, C row=seq)
// mode 1: out[(b*DOUT + r)*LEN + l] + bias[r]          (GEMM2, C row=nout, col=seq)
__global__ __launch_bounds__(NTHREADS)
void mma_gemm(const __nv_bfloat16* __restrict__ Ah, const __nv_bfloat16* __restrict__ Al,
              const __nv_bfloat16* __restrict__ Bh, const __nv_bfloat16* __restrict__ Bl,
              const float* __restrict__ bias, float* __restrict__ out,
              int K, int mode){
    extern __shared__ __align__(1024) char smem[];
    const uint32_t sb = s2u(smem);
    const int tid = threadIdx.x;
    const int wid = tid >> 5, lane = tid & 31;
    const int wm = (wid & 3) * 32;        // warp m offset (A rows)
    const int wn = (wid >> 2) * 64;       // warp n offset (B rows)
    const int m0 = blockIdx.y * BM;
    const int n0 = blockIdx.x * BN;
    const int NC = K / BK;

    // lane decomposition for ldmatrix addressing
    const int a_mi = lane >> 3, a_lr = lane & 7;
    const int a_roff = ((a_mi & 1) << 3) + a_lr;   // row offset within 16-row frag
    const int a_uoff = a_mi >> 1;                   // 16B-unit offset within k16
    const int b_l  = lane & 15;
    const int b_roff = b_l & 7;
    const int b_uoff = b_l >> 3;

    float acc[2][8][4];
    #pragma unroll
    for (int i = 0; i < 2; i++)
        #pragma unroll
        for (int j = 0; j < 8; j++)
            #pragma unroll
            for (int q = 0; q < 4; q++) acc[i][j][q] = 0.f;

    // prologue: fill stages for chunks 0..2
    #pragma unroll
    for (int c = 0; c < STAGES - 1; c++){
        fill_stage(sb + c*STAGE_BYTES, Ah, Al, Bh, Bl, K, m0, n0, c*BK, tid);
        CPA_COMMIT();
    }

    for (int c = 0; c < NC; c++){
        CPA_WAIT(STAGES - 2);
        __syncthreads();
        if (c + STAGES - 1 < NC)
            fill_stage(sb + ((c + STAGES - 1) % STAGES)*STAGE_BYTES,
                       Ah, Al, Bh, Bl, K, m0, n0, (c + STAGES - 1)*BK, tid);
        CPA_COMMIT();

        const uint32_t st = sb + (c % STAGES)*STAGE_BYTES;
        #pragma unroll
        for (int ks = 0; ks < 2; ks++){
            uint32_t ah[2][4], al[2][4], bh[8][2], bl[8][2];
            #pragma unroll
            for (int mf = 0; mf < 2; mf++){
                int row = wm + mf*16 + a_roff;
                int u = ks*2 + a_uoff;
                uint32_t sw = swz(row, u);
                ldm4(st + 0*MAT_BYTES + sw, ah[mf]);
                ldm4(st + 1*MAT_BYTES + sw, al[mf]);
            }
            #pragma unroll
            for (int nf = 0; nf < 8; nf++){
                int row = wn + nf*8 + b_roff;
                int u = ks*2 + b_uoff;
                uint32_t sw = swz(row, u);
                ldm2(st + 2*MAT_BYTES + sw, bh[nf]);
                ldm2(st + 3*MAT_BYTES + sw, bl[nf]);
            }
            #pragma unroll
            for (int mf = 0; mf < 2; mf++)
                #pragma unroll
                for (int nf = 0; nf < 8; nf++){
                    mma16816(acc[mf][nf], ah[mf], bh[nf]);
                    mma16816(acc[mf][nf], ah[mf], bl[nf]);
                    mma16816(acc[mf][nf], al[mf], bh[nf]);
                }
        }
        __syncthreads();
    }

    // epilogue
    const int gq = lane >> 2, c2 = (lane & 3) * 2;
    if (mode == 0){
        #pragma unroll
        for (int mf = 0; mf < 2; mf++){
            int r = m0 + wm + mf*16 + gq;
            #pragma unroll
            for (int nf = 0; nf < 8; nf++){
                int col = n0 + wn + nf*8 + c2;
                float b0 = __ldg(bias + col), b1 = __ldg(bias + col + 1);
                float2 v0 = make_float2(acc[mf][nf][0] + b0, acc[mf][nf][1] + b1);
                float2 v1 = make_float2(acc[mf][nf][2] + b0, acc[mf][nf][3] + b1);
                *reinterpret_cast<float2*>(&out[(size_t)r*DD + col]) = v0;
                *reinterpret_cast<float2*>(&out[(size_t)(r+8)*DD + col]) = v1;
            }
        }
    } else {
        #pragma unroll
        for (int mf = 0; mf < 2; mf++){
            int r = m0 + wm + mf*16 + gq;
            float br0 = __ldg(bias + r), br1 = __ldg(bias + r + 8);
            #pragma unroll
            for (int nf = 0; nf < 8; nf++){
                int col = n0 + wn + nf*8 + c2;     // sequence index
                int b = col >> 11, l = col & (LEN - 1);
                float* op0 = &out[((size_t)(b*DOUT + r))*LEN + l];
                float* op1 = &out[((size_t)(b*DOUT + r + 8))*LEN + l];
                *reinterpret_cast<float2*>(op0) =
                    make_float2(acc[mf][nf][0] + br0, acc[mf][nf][1] + br0);
                *reinterpret_cast<float2*>(op1) =
                    make_float2(acc[mf][nf][2] + br1, acc[mf][nf][3] + br1);
            }
        }
    }
}

// transpose + bf16 split: slab z of src [R][C] fp32 -> dst [C][R] bf16 hi/lo
__global__ __launch_bounds__(256)
void tsplit(const float* __restrict__ src, __nv_bfloat16* __restrict__ dhi,
            __nv_bfloat16* __restrict__ dlo, int R, int C){
    __shared__ float tile[32][33];
    const size_t zo = (size_t)blockIdx.z * R * C;
    const int c0 = blockIdx.x*32, r0 = blockIdx.y*32;
    #pragma unroll
    for (int i = threadIdx.y; i < 32; i += 8)
        tile[i][threadIdx.x] = src[zo + (size_t)(r0+i)*C + c0 + threadIdx.x];
    __syncthreads();
    #pragma unroll
    for (int i = threadIdx.y; i < 32; i += 8){
        float v = tile[threadIdx.x][i];
        __nv_bfloat16 h = __float2bfloat16(v);
        __nv_bfloat16 lo = __float2bfloat16(v - __bfloat162float(h));
        const size_t o = zo + (size_t)(c0+i)*R + r0 + threadIdx.x;
        dhi[o] = h; dlo[o] = lo;
    }
}

// window-3 softmax attention; emits bf16-split att
__global__ __launch_bounds__(256)
void attn_kernel(){
    for (int m = blockIdx.x; m < MM; m += gridDim.x){
        const int b = m >> 11, l = m & (LEN-1);
        const int head = threadIdx.x >> 5, lane = threadIdx.x & 31;
        const size_t base = (size_t)m*DD + head*64 + lane*2;
        const float2 q = *reinterpret_cast<const float2*>(&g_q[base]);
        float s[3]; float2 vv[3];
        #pragma unroll
        for (int w = 0; w < 3; w++){
            const int lw = l + w - 1;
            float2 kk = make_float2(0.f,0.f), v2 = make_float2(0.f,0.f);
            if (lw >= 0 && lw < LEN){
                const size_t off = (size_t)(b*LEN+lw)*DD + head*64 + lane*2;
                kk = *reinterpret_cast<const float2*>(&g_k[off]);
                v2 = *reinterpret_cast<const float2*>(&g_v[off]);
            }
            float p = q.x*kk.x + q.y*kk.y;
            #pragma unroll
            for (int o = 16; o; o >>= 1) p += __shfl_xor_sync(0xffffffffu, p, o);
            s[w] = p * 0.125f; vv[w] = v2;
        }
        const float mx = fmaxf(s[0], fmaxf(s[1], s[2]));
        const float e0 = __expf(s[0]-mx), e1 = __expf(s[1]-mx), e2 = __expf(s[2]-mx);
        const float inv = 1.f/(e0+e1+e2);
        const float ox = (e0*vv[0].x + e1*vv[1].x + e2*vv[2].x)*inv;
        const float oy = (e0*vv[0].y + e1*vv[1].y + e2*vv[2].y)*inv;
        __nv_bfloat16 hx = __float2bfloat16(ox), hy = __float2bfloat16(oy);
        __nv_bfloat162 hi; hi.x = hx; hi.y = hy;
        __nv_bfloat162 lo;
        lo.x = __float2bfloat16(ox - __bfloat162float(hx));
        lo.y = __float2bfloat16(oy - __bfloat162float(hy));
        *reinterpret_cast<__nv_bfloat162*>(&g_att_hi[base]) = hi;
        *reinterpret_cast<__nv_bfloat162*>(&g_att_lo[base]) = lo;
    }
}

extern "C" void kernel_launch(void* const* d_in, const int* in_sizes, int n_in,
                              void* d_out, int out_size){
    const float* x  = (const float*)d_in[0];
    const float* Wq = (const float*)d_in[1];
    const float* bq = (const float*)d_in[2];
    const float* Wk = (const float*)d_in[3];
    const float* bk = (const float*)d_in[4];
    const float* Wv = (const float*)d_in[5];
    const float* bv = (const float*)d_in[6];
    const float* Wo = (const float*)d_in[7];
    const float* bo = (const float*)d_in[8];
    float* out = (float*)d_out;

    void *xh,*xl,*qh,*ql,*kh,*kl,*vh,*vl,*oh,*ol,*ath,*atl,*pq,*pk,*pv;
    cudaGetSymbolAddress(&xh, g_xt_hi);  cudaGetSymbolAddress(&xl, g_xt_lo);
    cudaGetSymbolAddress(&qh, g_wq_hi);  cudaGetSymbolAddress(&ql, g_wq_lo);
    cudaGetSymbolAddress(&kh, g_wk_hi);  cudaGetSymbolAddress(&kl, g_wk_lo);
    cudaGetSymbolAddress(&vh, g_wv_hi);  cudaGetSymbolAddress(&vl, g_wv_lo);
    cudaGetSymbolAddress(&oh, g_wo_hi);  cudaGetSymbolAddress(&ol, g_wo_lo);
    cudaGetSymbolAddress(&ath, g_att_hi); cudaGetSymbolAddress(&atl, g_att_lo);
    cudaGetSymbolAddress(&pq, g_q); cudaGetSymbolAddress(&pk, g_k);
    cudaGetSymbolAddress(&pv, g_v);

    cudaFuncSetAttribute(mma_gemm, cudaFuncAttributeMaxDynamicSharedMemorySize, SMEM_BYTES);

    dim3 tb(32, 8);
    // x [B,NHID,LEN] -> xt [MM,NHID] bf16 hi/lo
    tsplit<<<dim3(LEN/32, NHID/32, BATCH), tb>>>(x, (__nv_bfloat16*)xh, (__nv_bfloat16*)xl, NHID, LEN);
    // W [NHID,DD] -> Wt [DD,NHID]
    tsplit<<<dim3(DD/32, NHID/32, 1), tb>>>(Wq, (__nv_bfloat16*)qh, (__nv_bfloat16*)ql, NHID, DD);
    tsplit<<<dim3(DD/32, NHID/32, 1), tb>>>(Wk, (__nv_bfloat16*)kh, (__nv_bfloat16*)kl, NHID, DD);
    tsplit<<<dim3(DD/32, NHID/32, 1), tb>>>(Wv, (__nv_bfloat16*)vh, (__nv_bfloat16*)vl, NHID, DD);
    // Wo [DD,DOUT] -> WoT [DOUT,DD]
    tsplit<<<dim3(DOUT/32, DD/32, 1), tb>>>(Wo, (__nv_bfloat16*)oh, (__nv_bfloat16*)ol, DD, DOUT);

    dim3 g1(DD/BN, MM/BM);
    mma_gemm<<<g1, NTHREADS, SMEM_BYTES>>>((__nv_bfloat16*)xh, (__nv_bfloat16*)xl,
        (__nv_bfloat16*)qh, (__nv_bfloat16*)ql, bq, (float*)pq, NHID, 0);
    mma_gemm<<<g1, NTHREADS, SMEM_BYTES>>>((__nv_bfloat16*)xh, (__nv_bfloat16*)xl,
        (__nv_bfloat16*)kh, (__nv_bfloat16*)kl, bk, (float*)pk, NHID, 0);
    mma_gemm<<<g1, NTHREADS, SMEM_BYTES>>>((__nv_bfloat16*)xh, (__nv_bfloat16*)xl,
        (__nv_bfloat16*)vh, (__nv_bfloat16*)vl, bv, (float*)pv, NHID, 0);

    attn_kernel<<<2048, 256>>>();

    // GEMM2: A=WoT rows nout (y), B=att rows seq (x); out [b, nout, l]
    dim3 g2(MM/BN, DOUT/BM);
    mma_gemm<<<g2, NTHREADS, SMEM_BYTES>>>((__nv_bfloat16*)oh, (__nv_bfloat16*)ol,
        (__nv_bfloat16*)ath, (__nv_bfloat16*)atl, bo, out, DD, 1);
}

// round 6
// speedup vs baseline: 2.4966x; 1.6562x over previous
#include <cuda_runtime.h>
#include <cuda_bf16.h>
#include <cstdint>

#define BATCH 8
#define NHID 256
#define LEN 2048
#define DD 512
#define DOUT 2048
#define MM (BATCH*LEN)

#define BM 128
#define BN 128
#define BK 32
#define NTHREADS 256
#define STAGES 3
#define MAT_BYTES 8192
#define STAGE_BYTES (4*MAT_BYTES)
#define SMEM_BYTES (STAGES*STAGE_BYTES)   // 96KB -> 2 CTA/SM

// fp32 scratch
__device__ __align__(128) float g_q[MM*DD];
__device__ __align__(128) float g_k[MM*DD];
__device__ __align__(128) float g_v[MM*DD];
// bf16 split operands
__device__ __align__(128) __nv_bfloat16 g_xt_hi[MM*NHID];
__device__ __align__(128) __nv_bfloat16 g_xt_lo[MM*NHID];
__device__ __align__(128) __nv_bfloat16 g_wq_hi[DD*NHID];
__device__ __align__(128) __nv_bfloat16 g_wq_lo[DD*NHID];
__device__ __align__(128) __nv_bfloat16 g_wk_hi[DD*NHID];
__device__ __align__(128) __nv_bfloat16 g_wk_lo[DD*NHID];
__device__ __align__(128) __nv_bfloat16 g_wv_hi[DD*NHID];
__device__ __align__(128) __nv_bfloat16 g_wv_lo[DD*NHID];
__device__ __align__(128) __nv_bfloat16 g_wo_hi[DOUT*DD];
__device__ __align__(128) __nv_bfloat16 g_wo_lo[DOUT*DD];
__device__ __align__(128) __nv_bfloat16 g_att_hi[MM*DD];
__device__ __align__(128) __nv_bfloat16 g_att_lo[MM*DD];

struct GemmArgs {
    const __nv_bfloat16* Ah; const __nv_bfloat16* Al;
    const __nv_bfloat16* Bh[3]; const __nv_bfloat16* Bl[3];
    const float* bias[3]; float* out[3];
};

__device__ __forceinline__ uint32_t s2u(const void* p){
    uint32_t a; asm("{ .reg .u64 t; cvta.to.shared.u64 t, %1; cvt.u32.u64 %0, t; }":"=r"(a):"l"(p)); return a; }
__device__ __forceinline__ void cpa16(uint32_t s, const void* g){
    asm volatile("cp.async.cg.shared.global [%0], [%1], 16;"::"r"(s),"l"(g):"memory"); }
#define CPA_COMMIT() asm volatile("cp.async.commit_group;":::"memory")
#define CPA_WAIT(n)  asm volatile("cp.async.wait_group %0;"::"n"(n):"memory")

__device__ __forceinline__ void ldm4(uint32_t a, uint32_t* r){
    asm volatile("ldmatrix.sync.aligned.m8n8.x4.shared.b16 {%0,%1,%2,%3}, [%4];"
        :"=r"(r[0]),"=r"(r[1]),"=r"(r[2]),"=r"(r[3]):"r"(a)); }
__device__ __forceinline__ void mma16816(float* d, const uint32_t* a,
                                         uint32_t b0, uint32_t b1){
    asm volatile("mma.sync.aligned.m16n8k16.row.col.f32.bf16.bf16.f32 "
        "{%0,%1,%2,%3}, {%4,%5,%6,%7}, {%8,%9}, {%0,%1,%2,%3};"
        :"+f"(d[0]),"+f"(d[1]),"+f"(d[2]),"+f"(d[3])
        :"r"(a[0]),"r"(a[1]),"r"(a[2]),"r"(a[3]),"r"(b0),"r"(b1)); }

// 16B-unit XOR swizzle: rows of 32 bf16 = 4 units; phys = r*4 + (u ^ ((r>>1)&3))
__device__ __forceinline__ uint32_t swz(int r, int u){
    return (uint32_t)((r*4 + (u ^ ((r>>1)&3))) * 16);
}

__device__ __forceinline__ void fill_stage(uint32_t sbase,
        const __nv_bfloat16* __restrict__ Ah, const __nv_bfloat16* __restrict__ Al,
        const __nv_bfloat16* __restrict__ Bh, const __nv_bfloat16* __restrict__ Bl,
        int K, int m0, int n0, int k0, int tid){
    #pragma unroll
    for (int j = 0; j < 2; j++){
        int i = tid + j*NTHREADS;          // 0..511
        int r = i >> 2, u = i & 3;
        uint32_t sw = swz(r, u);
        size_t gA = (size_t)(m0 + r)*K + k0 + u*8;
        size_t gB = (size_t)(n0 + r)*K + k0 + u*8;
        cpa16(sbase + 0*MAT_BYTES + sw, Ah + gA);
        cpa16(sbase + 1*MAT_BYTES + sw, Al + gA);
        cpa16(sbase + 2*MAT_BYTES + sw, Bh + gB);
        cpa16(sbase + 3*MAT_BYTES + sw, Bl + gB);
    }
}

// mode 0: out[(m0+r)*DD + col] + bias[col]     (GEMM1)
// mode 1: out[(b*DOUT + r)*LEN + l] + bias[r]  (GEMM2, col=seq)
__global__ __launch_bounds__(NTHREADS, 2)
void mma_gemm(const __grid_constant__ GemmArgs args, int K, int mode){
    extern __shared__ __align__(1024) char smem[];
    const int z = blockIdx.z;
    const __nv_bfloat16* __restrict__ Ah = args.Ah;
    const __nv_bfloat16* __restrict__ Al = args.Al;
    const __nv_bfloat16* __restrict__ Bh = args.Bh[z];
    const __nv_bfloat16* __restrict__ Bl = args.Bl[z];
    const float* __restrict__ bias = args.bias[z];
    float* __restrict__ out = args.out[z];

    const uint32_t sb = s2u(smem);
    const int tid = threadIdx.x;
    const int wid = tid >> 5, lane = tid & 31;
    const int wm = (wid & 3) * 32;        // warp m offset
    const int wn = (wid >> 2) * 64;       // warp n offset
    const int m0 = blockIdx.y * BM;
    const int n0 = blockIdx.x * BN;
    const int NC = K / BK;

    // ldmatrix lane decomposition (x4: groups of 8 lanes -> 4 matrices)
    const int g8 = lane >> 3;
    const int frag_row = ((g8 & 1) << 3) + (lane & 7);  // row within 16
    const int frag_u   = g8 >> 1;                       // 16B unit within k16

    float acc[2][8][4];
    #pragma unroll
    for (int i = 0; i < 2; i++)
        #pragma unroll
        for (int j = 0; j < 8; j++)
            #pragma unroll
            for (int q = 0; q < 4; q++) acc[i][j][q] = 0.f;

    #pragma unroll
    for (int c = 0; c < STAGES - 1; c++){
        fill_stage(sb + c*STAGE_BYTES, Ah, Al, Bh, Bl, K, m0, n0, c*BK, tid);
        CPA_COMMIT();
    }

    for (int c = 0; c < NC; c++){
        CPA_WAIT(STAGES - 2);
        __syncthreads();
        if (c + STAGES - 1 < NC)
            fill_stage(sb + ((c + STAGES - 1) % STAGES)*STAGE_BYTES,
                       Ah, Al, Bh, Bl, K, m0, n0, (c + STAGES - 1)*BK, tid);
        CPA_COMMIT();

        const uint32_t st = sb + (c % STAGES)*STAGE_BYTES;
        #pragma unroll
        for (int ks = 0; ks < 2; ks++){
            uint32_t ah[2][4], al[2][4];
            #pragma unroll
            for (int mf = 0; mf < 2; mf++){
                uint32_t sw = swz(wm + mf*16 + frag_row, ks*2 + frag_u);
                ldm4(st + 0*MAT_BYTES + sw, ah[mf]);
                ldm4(st + 1*MAT_BYTES + sw, al[mf]);
            }
            #pragma unroll
            for (int np = 0; np < 4; np++){
                uint32_t sw = swz(wn + np*16 + frag_row, ks*2 + frag_u);
                uint32_t b4h[4], b4l[4];
                ldm4(st + 2*MAT_BYTES + sw, b4h);
                ldm4(st + 3*MAT_BYTES + sw, b4l);
                #pragma unroll
                for (int mf = 0; mf < 2; mf++){
                    float* ae = acc[mf][np*2];
                    float* ao = acc[mf][np*2 + 1];
                    mma16816(ae, ah[mf], b4h[0], b4h[2]);
                    mma16816(ae, ah[mf], b4l[0], b4l[2]);
                    mma16816(ae, al[mf], b4h[0], b4h[2]);
                    mma16816(ao, ah[mf], b4h[1], b4h[3]);
                    mma16816(ao, ah[mf], b4l[1], b4l[3]);
                    mma16816(ao, al[mf], b4h[1], b4h[3]);
                }
            }
        }
        __syncthreads();
    }

    // epilogue
    const int gq = lane >> 2, c2 = (lane & 3) * 2;
    if (mode == 0){
        #pragma unroll
        for (int mf = 0; mf < 2; mf++){
            int r = m0 + wm + mf*16 + gq;
            #pragma unroll
            for (int nf = 0; nf < 8; nf++){
                int col = n0 + wn + nf*8 + c2;
                float b0 = __ldg(bias + col), b1 = __ldg(bias + col + 1);
                *reinterpret_cast<float2*>(&out[(size_t)r*DD + col]) =
                    make_float2(acc[mf][nf][0] + b0, acc[mf][nf][1] + b1);
                *reinterpret_cast<float2*>(&out[(size_t)(r+8)*DD + col]) =
                    make_float2(acc[mf][nf][2] + b0, acc[mf][nf][3] + b1);
            }
        }
    } else {
        #pragma unroll
        for (int mf = 0; mf < 2; mf++){
            int r = m0 + wm + mf*16 + gq;
            float br0 = __ldg(bias + r), br1 = __ldg(bias + r + 8);
            #pragma unroll
            for (int nf = 0; nf < 8; nf++){
                int col = n0 + wn + nf*8 + c2;     // sequence index
                int b = col >> 11, l = col & (LEN - 1);
                *reinterpret_cast<float2*>(&out[((size_t)(b*DOUT + r))*LEN + l]) =
                    make_float2(acc[mf][nf][0] + br0, acc[mf][nf][1] + br0);
                *reinterpret_cast<float2*>(&out[((size_t)(b*DOUT + r + 8))*LEN + l]) =
                    make_float2(acc[mf][nf][2] + br1, acc[mf][nf][3] + br1);
            }
        }
    }
}

// transpose + bf16 split: slab z of src [R][C] fp32 -> dst [C][R] bf16 hi/lo
__global__ __launch_bounds__(256)
void tsplit(const float* __restrict__ src, __nv_bfloat16* __restrict__ dhi,
            __nv_bfloat16* __restrict__ dlo, int R, int C){
    __shared__ float tile[32][33];
    const size_t zo = (size_t)blockIdx.z * R * C;
    const int c0 = blockIdx.x*32, r0 = blockIdx.y*32;
    #pragma unroll
    for (int i = threadIdx.y; i < 32; i += 8)
        tile[i][threadIdx.x] = src[zo + (size_t)(r0+i)*C + c0 + threadIdx.x];
    __syncthreads();
    #pragma unroll
    for (int i = threadIdx.y; i < 32; i += 8){
        float v = tile[threadIdx.x][i];
        __nv_bfloat16 h = __float2bfloat16(v);
        __nv_bfloat16 lo = __float2bfloat16(v - __bfloat162float(h));
        const size_t o = zo + (size_t)(c0+i)*R + r0 + threadIdx.x;
        dhi[o] = h; dlo[o] = lo;
    }
}

// window-3 softmax attention; emits bf16-split att
__global__ __launch_bounds__(256)
void attn_kernel(){
    for (int m = blockIdx.x; m < MM; m += gridDim.x){
        const int b = m >> 11, l = m & (LEN-1);
        const int head = threadIdx.x >> 5, lane = threadIdx.x & 31;
        const size_t base = (size_t)m*DD + head*64 + lane*2;
        const float2 q = *reinterpret_cast<const float2*>(&g_q[base]);
        float s[3]; float2 vv[3];
        #pragma unroll
        for (int w = 0; w < 3; w++){
            const int lw = l + w - 1;
            float2 kk = make_float2(0.f,0.f), v2 = make_float2(0.f,0.f);
            if (lw >= 0 && lw < LEN){
                const size_t off = (size_t)(b*LEN+lw)*DD + head*64 + lane*2;
                kk = *reinterpret_cast<const float2*>(&g_k[off]);
                v2 = *reinterpret_cast<const float2*>(&g_v[off]);
            }
            float p = q.x*kk.x + q.y*kk.y;
            #pragma unroll
            for (int o = 16; o; o >>= 1) p += __shfl_xor_sync(0xffffffffu, p, o);
            s[w] = p * 0.125f; vv[w] = v2;
        }
        const float mx = fmaxf(s[0], fmaxf(s[1], s[2]));
        const float e0 = __expf(s[0]-mx), e1 = __expf(s[1]-mx), e2 = __expf(s[2]-mx);
        const float inv = 1.f/(e0+e1+e2);
        const float ox = (e0*vv[0].x + e1*vv[1].x + e2*vv[2].x)*inv;
        const float oy = (e0*vv[0].y + e1*vv[1].y + e2*vv[2].y)*inv;
        __nv_bfloat16 hx = __float2bfloat16(ox), hy = __float2bfloat16(oy);
        __nv_bfloat162 hi; hi.x = hx; hi.y = hy;
        __nv_bfloat162 lo;
        lo.x = __float2bfloat16(ox - __bfloat162float(hx));
        lo.y = __float2bfloat16(oy - __bfloat162float(hy));
        *reinterpret_cast<__nv_bfloat162*>(&g_att_hi[base]) = hi;
        *reinterpret_cast<__nv_bfloat162*>(&g_att_lo[base]) = lo;
    }
}

extern "C" void kernel_launch(void* const* d_in, const int* in_sizes, int n_in,
                              void* d_out, int out_size){
    const float* x  = (const float*)d_in[0];
    const float* Wq = (const float*)d_in[1];
    const float* bq = (const float*)d_in[2];
    const float* Wk = (const float*)d_in[3];
    const float* bk = (const float*)d_in[4];
    const float* Wv = (const float*)d_in[5];
    const float* bv = (const float*)d_in[6];
    const float* Wo = (const float*)d_in[7];
    const float* bo = (const float*)d_in[8];
    float* out = (float*)d_out;

    void *xh,*xl,*qh,*ql,*kh,*kl,*vh,*vl,*oh,*ol,*ath,*atl,*pq,*pk,*pv;
    cudaGetSymbolAddress(&xh, g_xt_hi);  cudaGetSymbolAddress(&xl, g_xt_lo);
    cudaGetSymbolAddress(&qh, g_wq_hi);  cudaGetSymbolAddress(&ql, g_wq_lo);
    cudaGetSymbolAddress(&kh, g_wk_hi);  cudaGetSymbolAddress(&kl, g_wk_lo);
    cudaGetSymbolAddress(&vh, g_wv_hi);  cudaGetSymbolAddress(&vl, g_wv_lo);
    cudaGetSymbolAddress(&oh, g_wo_hi);  cudaGetSymbolAddress(&ol, g_wo_lo);
    cudaGetSymbolAddress(&ath, g_att_hi); cudaGetSymbolAddress(&atl, g_att_lo);
    cudaGetSymbolAddress(&pq, g_q); cudaGetSymbolAddress(&pk, g_k);
    cudaGetSymbolAddress(&pv, g_v);

    cudaFuncSetAttribute(mma_gemm, cudaFuncAttributeMaxDynamicSharedMemorySize, SMEM_BYTES);

    dim3 tb(32, 8);
    tsplit<<<dim3(LEN/32, NHID/32, BATCH), tb>>>(x, (__nv_bfloat16*)xh, (__nv_bfloat16*)xl, NHID, LEN);
    tsplit<<<dim3(DD/32, NHID/32, 1), tb>>>(Wq, (__nv_bfloat16*)qh, (__nv_bfloat16*)ql, NHID, DD);
    tsplit<<<dim3(DD/32, NHID/32, 1), tb>>>(Wk, (__nv_bfloat16*)kh, (__nv_bfloat16*)kl, NHID, DD);
    tsplit<<<dim3(DD/32, NHID/32, 1), tb>>>(Wv, (__nv_bfloat16*)vh, (__nv_bfloat16*)vl, NHID, DD);
    tsplit<<<dim3(DOUT/32, DD/32, 1), tb>>>(Wo, (__nv_bfloat16*)oh, (__nv_bfloat16*)ol, DD, DOUT);

    // fused QKV: grid.z selects weight/bias/output
    GemmArgs a1;
    a1.Ah = (const __nv_bfloat16*)xh; a1.Al = (const __nv_bfloat16*)xl;
    a1.Bh[0] = (const __nv_bfloat16*)qh; a1.Bl[0] = (const __nv_bfloat16*)ql;
    a1.Bh[1] = (const __nv_bfloat16*)kh; a1.Bl[1] = (const __nv_bfloat16*)kl;
    a1.Bh[2] = (const __nv_bfloat16*)vh; a1.Bl[2] = (const __nv_bfloat16*)vl;
    a1.bias[0] = bq; a1.bias[1] = bk; a1.bias[2] = bv;
    a1.out[0] = (float*)pq; a1.out[1] = (float*)pk; a1.out[2] = (float*)pv;
    mma_gemm<<<dim3(DD/BN, MM/BM, 3), NTHREADS, SMEM_BYTES>>>(a1, NHID, 0);

    attn_kernel<<<2048, 256>>>();

    // GEMM2: A=WoT rows nout (y), B=att rows seq (x); out [b, nout, l]
    GemmArgs a2;
    a2.Ah = (const __nv_bfloat16*)oh; a2.Al = (const __nv_bfloat16*)ol;
    a2.Bh[0] = (const __nv_bfloat16*)ath; a2.Bl[0] = (const __nv_bfloat16*)atl;
    a2.Bh[1] = a2.Bh[0]; a2.Bl[1] = a2.Bl[0];
    a2.Bh[2] = a2.Bh[0]; a2.Bl[2] = a2.Bl[0];
    a2.bias[0] = bo; a2.bias[1] = bo; a2.bias[2] = bo;
    a2.out[0] = out; a2.out[1] = out; a2.out[2] = out;
    mma_gemm<<<dim3(MM/BN, DOUT/BM, 1), NTHREADS, SMEM_BYTES>>>(a2, DD, 1);
}